// round 16
// baseline (speedup 1.0000x reference)
#include <cuda_runtime.h>
#include <cuda_bf16.h>
#include <cstdint>

#define NPTS 1024
#define HDIM 32
#define TCH 8
#define NCH (NPTS / TCH)

// dynamic smem layout (bytes):
//   xg ring [2][8 seq][TCH][100 f]  : 0      .. 51200
//   hg      [8 seq][100 f]          : 51200  .. 54400
//   hv      [8 seq][36 f]           : 54400  .. 55552
#define SMEM_TOT 55552

typedef unsigned long long u64;
typedef unsigned int u32;

// ---------- scratch ----------
__device__ float g_a[NPTS * HDIM];
__device__ float g_c[(NPTS + 8) * HDIM];   // zero pad rows
__device__ float g_h1[NPTS * HDIM];

// ---------- helpers ----------
__device__ __forceinline__ u64 pack2(float lo, float hi) {
    u64 r;
    asm("mov.b64 %0, {%1, %2};" : "=l"(r) : "f"(lo), "f"(hi));
    return r;
}
__device__ __forceinline__ float tanh_hw(float x) {
    float y;
    asm("tanh.approx.f32 %0, %1;" : "=f"(y) : "f"(x));
    return y;
}
__device__ __forceinline__ float sig_hw(float x) {
    return fmaf(tanh_hw(0.5f * x), 0.5f, 0.5f);
}
__device__ __forceinline__ u32 smem_u32(const void* p) {
    u32 a;
    asm("{ .reg .u64 t; cvta.to.shared.u64 t, %1; cvt.u32.u64 %0, t; }"
        : "=r"(a) : "l"(p));
    return a;
}
__device__ __forceinline__ void sts32(u32 addr, float v) {
    asm volatile("st.shared.b32 [%0], %1;" :: "r"(addr), "f"(v) : "memory");
}
__device__ __forceinline__ void sts64(u32 addr, u64 v) {
    asm volatile("st.shared.b64 [%0], %1;" :: "r"(addr), "l"(v) : "memory");
}
__device__ __forceinline__ float lds32f(u32 addr) {
    float v;
    asm volatile("ld.shared.b32 %0, [%1];" : "=f"(v) : "r"(addr));
    return v;
}
__device__ __forceinline__ u32 tf32_of(float x) {
    u32 r;
    asm("cvt.rna.tf32.f32 %0, %1;" : "=r"(r) : "f"(x));
    return r;
}
__device__ __forceinline__ void mma_tf32(float& c0, float& c1, float& c2, float& c3,
                                         u32 a0, u32 a1, u32 a2, u32 a3,
                                         u32 b0, u32 b1) {
    asm("mma.sync.aligned.m16n8k8.row.col.f32.tf32.tf32.f32 "
        "{%0,%1,%2,%3}, {%4,%5,%6,%7}, {%8,%9}, {%0,%1,%2,%3};"
        : "+f"(c0), "+f"(c1), "+f"(c2), "+f"(c3)
        : "r"(a0), "r"(a1), "r"(a2), "r"(a3), "r"(b0), "r"(b1));
}

// ---------- precompute: a_i = (Wa-Wb)@x_i + b ; c_j = Wb@x_j ----------
template <int F>
__global__ void __launch_bounds__(256)
pre_kernel(const float* __restrict__ x, const float* __restrict__ w,
           const float* __restrict__ b, float* __restrict__ a,
           float* __restrict__ c) {
    int wq = threadIdx.x >> 5;
    int l = threadIdx.x & 31;
    int i = blockIdx.x * 8 + wq;
    if (i >= NPTS) return;
    float av = b[l];
    float cv = 0.0f;
    const float* wr = w + l * (2 * F);
    const float* xr = x + i * F;
#pragma unroll
    for (int f = 0; f < F; ++f) {
        float xv = xr[f];
        float wa = wr[f];
        float wb = wr[F + f];
        av = fmaf(wa - wb, xv, av);
        cv = fmaf(wb, xv, cv);
    }
    a[i * HDIM + l] = av;
    c[i * HDIM + l] = cv;
}

// ---------- ping-pong GRU: hg AND xg on tensor cores ----------
// 256 thr: warps 0-3 = tail (2 seqs each, gates only); warps 4-7 = MMA.
// Per step: syncA -> MMA warps batch hg_j = Whh(tf32) @ [hi(h);lo(h)] for all
// 8 seqs -> syncB -> tails do gates/recurrence while MMA warps compute the
// next chunk's xg slice (R14 layout). xg lives only in a smem ring.
template <int FUSE_CLF>
__global__ void __launch_bounds__(256, 1)
gru_pp_kernel(const float* __restrict__ a, const float* __restrict__ c,
              const float* __restrict__ wih, const float* __restrict__ whh,
              const float* __restrict__ bih, const float* __restrict__ bhh,
              const float* __restrict__ clf_w, const float* __restrict__ clf_b,
              float* __restrict__ out) {
    extern __shared__ __align__(16) char dsm[];
    const u32 xgb = smem_u32(dsm);
    const u32 hgb = xgb + 51200u;
    const u32 hvb = xgb + 54400u;

    const int wid = threadIdx.x >> 5;
    const int l = threadIdx.x & 31;

    if (wid < 4) {
        // ===================== tail (2 seqs) =====================
        const int sA = 2 * wid, sB = sA + 1;
        const int iA = blockIdx.x * 8 + sA;
        const int iB = iA + 1;
        const float b_r = bih[l] + bhh[l];
        const float b_z = bih[HDIM + l] + bhh[HDIM + l];
        const float b_xn = bih[2 * HDIM + l];
        const float b_hn = bhh[2 * HDIM + l];

        const u32 hvA = hvb + (u32)sA * 144u + (u32)l * 4u;
        const u32 hvB = hvb + (u32)sB * 144u + (u32)l * 4u;
        const u32 xA = xgb + (u32)sA * 3200u + (u32)l * 4u;
        const u32 xB = xgb + (u32)sB * 3200u + (u32)l * 4u;
        const u32 hgA = hgb + (u32)sA * 400u + (u32)l * 4u;
        const u32 hgB = hgb + (u32)sB * 400u + (u32)l * 4u;

        float hA = 0.0f, hB = 0.0f;
        sts32(hvA, 0.0f);
        sts32(hvB, 0.0f);
        __syncthreads();                       // pairs with producer prologue

        for (int k = 0; k < NCH; ++k) {
            const u32 boff = (u32)(k & 1) * 25600u;
#pragma unroll 2
            for (int t = 0; t < TCH; ++t) {
                __syncthreads();               // sync_A: hv=h_j visible, hg free
                const u32 xoA = xA + boff + (u32)t * 400u;
                const u32 xoB = xB + boff + (u32)t * 400u;
                const float xrA = lds32f(xoA);
                const float xzA = lds32f(xoA + 128u);
                const float xnA = lds32f(xoA + 256u);
                const float xrB = lds32f(xoB);
                const float xzB = lds32f(xoB + 128u);
                const float xnB = lds32f(xoB + 256u);
                __syncthreads();               // sync_B: hg_j ready
                const float hrA = lds32f(hgA);
                const float hzA = lds32f(hgA + 128u);
                const float hnA = lds32f(hgA + 256u);
                const float hrB = lds32f(hgB);
                const float hzB = lds32f(hgB + 128u);
                const float hnB = lds32f(hgB + 256u);
                const float rA = sig_hw(xrA + hrA + b_r);
                const float zA = sig_hw(xzA + hzA + b_z);
                const float nA = tanh_hw(fmaf(rA, hnA + b_hn, xnA + b_xn));
                hA = fmaf(zA, hA - nA, nA);
                const float rB = sig_hw(xrB + hrB + b_r);
                const float zB = sig_hw(xzB + hzB + b_z);
                const float nB = tanh_hw(fmaf(rB, hnB + b_hn, xnB + b_xn));
                hB = fmaf(zB, hB - nB, nB);
                sts32(hvA, hA);
                sts32(hvB, hB);
            }
        }

        __syncwarp();
        if (FUSE_CLF) {
            if (l < 3) {
                float accA = clf_b[l];
                float accB = clf_b[l];
                const float* cw = clf_w + l * HDIM;
#pragma unroll
                for (int hh = 0; hh < HDIM; ++hh) {
                    accA = fmaf(cw[hh], lds32f(hvb + (u32)sA * 144u + (u32)hh * 4u), accA);
                    accB = fmaf(cw[hh], lds32f(hvb + (u32)sB * 144u + (u32)hh * 4u), accB);
                }
                out[iA * 3 + l] = accA;
                out[iB * 3 + l] = accB;
            }
        } else {
            out[iA * HDIM + l] = hA;
            out[iB * HDIM + l] = hB;
        }
    } else {
        // ===================== MMA warp =====================
        const int m = wid - 4;                 // 0..3
        const int g = l >> 2, tig = l & 3;

        // Whh fragments for this warp's 3 hg n-tiles (nt = 3m+nn)
        u32 WB[3][4][2];
#pragma unroll
        for (int nn = 0; nn < 3; ++nn) {
            const float* wr = whh + ((3 * m + nn) * 8 + g) * HDIM;
#pragma unroll
            for (int kc = 0; kc < 4; ++kc) {
                WB[nn][kc][0] = tf32_of(wr[kc * 8 + tig]);
                WB[nn][kc][1] = tf32_of(wr[kc * 8 + tig + 4]);
            }
        }
        // Wih fragments (all 12 n-tiles) for xg production
        u32 XB[12][4][2];
#pragma unroll
        for (int nt = 0; nt < 12; ++nt) {
            const float* wr = wih + (nt * 8 + g) * HDIM;
#pragma unroll
            for (int kc = 0; kc < 4; ++kc) {
                XB[nt][kc][0] = tf32_of(wr[kc * 8 + tig]);
                XB[nt][kc][1] = tf32_of(wr[kc * 8 + tig + 4]);
            }
        }
        const int s0 = 2 * m, s1 = s0 + 1;
        const int i0 = blockIdx.x * 8 + s0;
        const int i1 = i0 + 1;
        float av00[4], av01[4], av10[4], av11[4];
#pragma unroll
        for (int kc = 0; kc < 4; ++kc) {
            av00[kc] = a[i0 * HDIM + kc * 8 + tig];
            av01[kc] = a[i0 * HDIM + kc * 8 + tig + 4];
            av10[kc] = a[i1 * HDIM + kc * 8 + tig];
            av11[kc] = a[i1 * HDIM + kc * 8 + tig + 4];
        }

        // ---- prologue: full xg production of chunk 0 into buf 0 ----
#pragma unroll
        for (int half = 0; half < 2; ++half) {
            float acc[6][4];
#pragma unroll
            for (int nn = 0; nn < 6; ++nn)
                acc[nn][0] = acc[nn][1] = acc[nn][2] = acc[nn][3] = 0.0f;
#pragma unroll
            for (int kc = 0; kc < 4; ++kc) {
                const float* cr = c + g * HDIM;
                const float cv0 = cr[kc * 8 + tig];
                const float cv1 = cr[kc * 8 + tig + 4];
                const float u0 = fmaxf(av00[kc] + cv0, 0.0f);
                const float u1 = fmaxf(av10[kc] + cv0, 0.0f);
                const float u2 = fmaxf(av01[kc] + cv1, 0.0f);
                const float u3 = fmaxf(av11[kc] + cv1, 0.0f);
                const u32 h0 = tf32_of(u0), h1 = tf32_of(u1);
                const u32 h2 = tf32_of(u2), h3 = tf32_of(u3);
                const u32 o0 = tf32_of(u0 - __uint_as_float(h0));
                const u32 o1 = tf32_of(u1 - __uint_as_float(h1));
                const u32 o2 = tf32_of(u2 - __uint_as_float(h2));
                const u32 o3 = tf32_of(u3 - __uint_as_float(h3));
#pragma unroll
                for (int nn = 0; nn < 6; ++nn) {
                    const int nt = half * 6 + nn;
                    mma_tf32(acc[nn][0], acc[nn][1], acc[nn][2], acc[nn][3],
                             h0, h1, h2, h3, XB[nt][kc][0], XB[nt][kc][1]);
                    mma_tf32(acc[nn][0], acc[nn][1], acc[nn][2], acc[nn][3],
                             o0, o1, o2, o3, XB[nt][kc][0], XB[nt][kc][1]);
                }
            }
            const u32 base0 = xgb + (u32)s0 * 3200u + (u32)g * 400u;
            const u32 base1 = xgb + (u32)s1 * 3200u + (u32)g * 400u;
#pragma unroll
            for (int nn = 0; nn < 6; ++nn) {
                const int nt = half * 6 + nn;
                const u32 cb = (u32)(nt * 8 + 2 * tig) * 4u;
                sts64(base0 + cb, pack2(acc[nn][0], acc[nn][1]));
                sts64(base1 + cb, pack2(acc[nn][2], acc[nn][3]));
            }
        }
        __syncthreads();                       // pairs with tail init sync

        float xacc[6][4];
        const u32 hvg = hvb + (u32)g * 144u;
        const u32 hgg = hgb + (u32)g * 400u;

        for (int k = 0; k < NCH; ++k) {
#pragma unroll 2
            for (int t = 0; t < TCH; ++t) {
                __syncthreads();               // sync_A
                // ---- hg for all 8 seqs: A rows 0-7 = hi(h_s), 8-15 = lo(h_s)
                float hacc[3][4];
#pragma unroll
                for (int nn = 0; nn < 3; ++nn)
                    hacc[nn][0] = hacc[nn][1] = hacc[nn][2] = hacc[nn][3] = 0.0f;
#pragma unroll
                for (int kc = 0; kc < 4; ++kc) {
                    const float v0 = lds32f(hvg + (u32)(kc * 8 + tig) * 4u);
                    const float v1 = lds32f(hvg + (u32)(kc * 8 + tig + 4) * 4u);
                    const u32 a0 = tf32_of(v0);
                    const u32 a2 = tf32_of(v1);
                    const u32 a1 = tf32_of(v0 - __uint_as_float(a0));
                    const u32 a3 = tf32_of(v1 - __uint_as_float(a2));
#pragma unroll
                    for (int nn = 0; nn < 3; ++nn)
                        mma_tf32(hacc[nn][0], hacc[nn][1], hacc[nn][2], hacc[nn][3],
                                 a0, a1, a2, a3, WB[nn][kc][0], WB[nn][kc][1]);
                }
#pragma unroll
                for (int nn = 0; nn < 3; ++nn) {
                    const u32 cb = (u32)((3 * m + nn) * 8 + 2 * tig) * 4u;
                    sts64(hgg + cb, pack2(hacc[nn][0] + hacc[nn][2],
                                          hacc[nn][1] + hacc[nn][3]));
                }
                __syncthreads();               // sync_B
                // ---- xg slice for chunk k+1 (overlaps tail phase) ----
                if (k + 1 < NCH) {
                    const int half = t >> 2, kc = t & 3;
                    if (kc == 0) {
#pragma unroll
                        for (int nn = 0; nn < 6; ++nn)
                            xacc[nn][0] = xacc[nn][1] = xacc[nn][2] = xacc[nn][3] = 0.0f;
                    }
                    const float* cr = c + ((k + 1) * TCH + g) * HDIM;
                    const float cv0 = cr[kc * 8 + tig];
                    const float cv1 = cr[kc * 8 + tig + 4];
                    const float u0 = fmaxf(av00[kc] + cv0, 0.0f);
                    const float u1 = fmaxf(av10[kc] + cv0, 0.0f);
                    const float u2 = fmaxf(av01[kc] + cv1, 0.0f);
                    const float u3 = fmaxf(av11[kc] + cv1, 0.0f);
                    const u32 h0 = tf32_of(u0), h1 = tf32_of(u1);
                    const u32 h2 = tf32_of(u2), h3 = tf32_of(u3);
                    const u32 o0 = tf32_of(u0 - __uint_as_float(h0));
                    const u32 o1 = tf32_of(u1 - __uint_as_float(h1));
                    const u32 o2 = tf32_of(u2 - __uint_as_float(h2));
                    const u32 o3 = tf32_of(u3 - __uint_as_float(h3));
#pragma unroll
                    for (int nn = 0; nn < 6; ++nn) {
                        const int nt = half * 6 + nn;
                        mma_tf32(xacc[nn][0], xacc[nn][1], xacc[nn][2], xacc[nn][3],
                                 h0, h1, h2, h3, XB[nt][kc][0], XB[nt][kc][1]);
                        mma_tf32(xacc[nn][0], xacc[nn][1], xacc[nn][2], xacc[nn][3],
                                 o0, o1, o2, o3, XB[nt][kc][0], XB[nt][kc][1]);
                    }
                    if (kc == 3) {
                        const u32 b2 = xgb + (u32)((k + 1) & 1) * 25600u;
                        const u32 base0 = b2 + (u32)s0 * 3200u + (u32)g * 400u;
                        const u32 base1 = b2 + (u32)s1 * 3200u + (u32)g * 400u;
#pragma unroll
                        for (int nn = 0; nn < 6; ++nn) {
                            const int nt = half * 6 + nn;
                            const u32 cb = (u32)(nt * 8 + 2 * tig) * 4u;
                            sts64(base0 + cb, pack2(xacc[nn][0], xacc[nn][1]));
                            sts64(base1 + cb, pack2(xacc[nn][2], xacc[nn][3]));
                        }
                    }
                }
            }
        }
    }
}

extern "C" void kernel_launch(void* const* d_in, const int* in_sizes, int n_in,
                              void* d_out, int out_size) {
    const float* x        = (const float*)d_in[0];
    const float* proj1_w  = (const float*)d_in[1];
    const float* proj1_b  = (const float*)d_in[2];
    const float* gru1_wih = (const float*)d_in[3];
    const float* gru1_whh = (const float*)d_in[4];
    const float* gru1_bih = (const float*)d_in[5];
    const float* gru1_bhh = (const float*)d_in[6];
    const float* proj2_w  = (const float*)d_in[7];
    const float* proj2_b  = (const float*)d_in[8];
    const float* gru2_wih = (const float*)d_in[9];
    const float* gru2_whh = (const float*)d_in[10];
    const float* gru2_bih = (const float*)d_in[11];
    const float* gru2_bhh = (const float*)d_in[12];
    const float* clf_w    = (const float*)d_in[13];
    const float* clf_b    = (const float*)d_in[14];
    float* out = (float*)d_out;

    float *pa, *pc, *ph1;
    cudaGetSymbolAddress((void**)&pa, g_a);
    cudaGetSymbolAddress((void**)&pc, g_c);
    cudaGetSymbolAddress((void**)&ph1, g_h1);

    cudaFuncSetAttribute(gru_pp_kernel<0>,
                         cudaFuncAttributeMaxDynamicSharedMemorySize, SMEM_TOT);
    cudaFuncSetAttribute(gru_pp_kernel<1>,
                         cudaFuncAttributeMaxDynamicSharedMemorySize, SMEM_TOT);

    // Stage 1
    pre_kernel<16><<<128, 256>>>(x, proj1_w, proj1_b, pa, pc);
    gru_pp_kernel<0><<<128, 256, SMEM_TOT>>>(pa, pc, gru1_wih, gru1_whh,
                                             gru1_bih, gru1_bhh,
                                             nullptr, nullptr, ph1);
    // Stage 2
    pre_kernel<32><<<128, 256>>>(ph1, proj2_w, proj2_b, pa, pc);
    gru_pp_kernel<1><<<128, 256, SMEM_TOT>>>(pa, pc, gru2_wih, gru2_whh,
                                             gru2_bih, gru2_bhh,
                                             clf_w, clf_b, out);
}